// round 10
// baseline (speedup 1.0000x reference)
#include <cuda_runtime.h>
#include <cstdint>

#define M_DIM 8192
#define N_DIM 16384
#define K_DIM 4096

// ---------------- device scratch (no allocations allowed) ----------------
__device__ int8_t g_xq8[(size_t)M_DIM * K_DIM];   // 32 MB quantized activations (ints)
__device__ int8_t g_wq8[(size_t)N_DIM * K_DIM];   // 64 MB ternary weights
__device__ float g_gamma[M_DIM];
__device__ float g_partial[1024];
__device__ float g_alpha;

// ---------------- helpers ----------------
__device__ __forceinline__ uint32_t smem_u32(const void* p) {
    uint32_t a;
    asm("{ .reg .u64 t; cvta.to.shared.u64 t, %1; cvt.u32.u64 %0, t; }" : "=r"(a) : "l"(p));
    return a;
}
__device__ __forceinline__ void cp_async16(uint32_t s, const void* g) {
    asm volatile("cp.async.cg.shared.global [%0], [%1], 16;" :: "r"(s), "l"(g) : "memory");
}
__device__ __forceinline__ void mma_s8(int* c, const uint32_t* a, const uint32_t* b) {
    asm volatile(
        "mma.sync.aligned.m16n8k32.row.col.s32.s8.s8.s32 "
        "{%0,%1,%2,%3}, {%4,%5,%6,%7}, {%8,%9}, {%0,%1,%2,%3};"
        : "+r"(c[0]), "+r"(c[1]), "+r"(c[2]), "+r"(c[3])
        : "r"(a[0]), "r"(a[1]), "r"(a[2]), "r"(a[3]), "r"(b[0]), "r"(b[1]));
}

// ---------------- kernel 1: partial sums of |w| (fixed order -> deterministic) ----------------
__global__ __launch_bounds__(256) void absmean_partial_kernel(const float* __restrict__ w) {
    __shared__ float red[256];
    const float4* w4 = reinterpret_cast<const float4*>(w);
    float s = 0.f;
    const int stride = gridDim.x * blockDim.x;
    for (int i = blockIdx.x * blockDim.x + threadIdx.x; i < 16777216; i += stride) {
        float4 v = w4[i];
        s += fabsf(v.x) + fabsf(v.y) + fabsf(v.z) + fabsf(v.w);
    }
    red[threadIdx.x] = s;
    __syncthreads();
    for (int o = 128; o > 0; o >>= 1) {
        if (threadIdx.x < (unsigned)o) red[threadIdx.x] += red[threadIdx.x + o];
        __syncthreads();
    }
    if (threadIdx.x == 0) g_partial[blockIdx.x] = red[0];
}

// ---------------- kernel 2: alpha ----------------
__global__ __launch_bounds__(256) void absmean_final_kernel() {
    __shared__ float red[256];
    float s = 0.f;
#pragma unroll
    for (int t = 0; t < 4; ++t) s += g_partial[threadIdx.x + t * 256];
    red[threadIdx.x] = s;
    __syncthreads();
    for (int o = 128; o > 0; o >>= 1) {
        if (threadIdx.x < (unsigned)o) red[threadIdx.x] += red[threadIdx.x + o];
        __syncthreads();
    }
    if (threadIdx.x == 0) g_alpha = red[0] * (1.0f / 67108864.0f) + 1e-8f;
}

// ---------------- kernel 3: ternary weight quant -> s8 ----------------
__global__ __launch_bounds__(256) void quant_w_kernel(const float* __restrict__ w) {
    const float inv_a = 1.0f / g_alpha;
    const float4* w4 = reinterpret_cast<const float4*>(w);
    uint32_t* dst = reinterpret_cast<uint32_t*>(g_wq8);
    const int stride = gridDim.x * blockDim.x;
    for (int i = blockIdx.x * blockDim.x + threadIdx.x; i < 16777216; i += stride) {
        float4 v = w4[i];
        int r0 = min(max(__float2int_rn(v.x * inv_a), -1), 1);
        int r1 = min(max(__float2int_rn(v.y * inv_a), -1), 1);
        int r2 = min(max(__float2int_rn(v.z * inv_a), -1), 1);
        int r3 = min(max(__float2int_rn(v.w * inv_a), -1), 1);
        dst[i] = (uint32_t)(uint8_t)r0 | ((uint32_t)(uint8_t)r1 << 8) |
                 ((uint32_t)(uint8_t)r2 << 16) | ((uint32_t)(uint8_t)r3 << 24);
    }
}

// ---------------- kernel 4: per-row gamma + activation quant -> s8 ----------------
__global__ __launch_bounds__(256) void quant_x_kernel(const float* __restrict__ x) {
    __shared__ float red[256];
    const int row = blockIdx.x;
    const int tid = threadIdx.x;
    const float4* xr = reinterpret_cast<const float4*>(x + (size_t)row * K_DIM);
    float4 v[4];
    float mx = 0.f;
#pragma unroll
    for (int t = 0; t < 4; ++t) {
        v[t] = xr[tid + t * 256];
        mx = fmaxf(mx, fmaxf(fmaxf(fabsf(v[t].x), fabsf(v[t].y)),
                             fmaxf(fabsf(v[t].z), fabsf(v[t].w))));
    }
    red[tid] = mx;
    __syncthreads();
    for (int o = 128; o > 0; o >>= 1) {
        if (tid < (unsigned)o) red[tid] = fmaxf(red[tid], red[tid + o]);
        __syncthreads();
    }
    const float gamma = fmaxf(red[0], 1e-8f);
    if (tid == 0) g_gamma[row] = gamma;
    const float sc = 127.0f / gamma;
    uint32_t* dst = reinterpret_cast<uint32_t*>(g_xq8 + (size_t)row * K_DIM);
#pragma unroll
    for (int t = 0; t < 4; ++t) {
        int r0 = __float2int_rn(v[t].x * sc);
        int r1 = __float2int_rn(v[t].y * sc);
        int r2 = __float2int_rn(v[t].z * sc);
        int r3 = __float2int_rn(v[t].w * sc);
        dst[tid + t * 256] = (uint32_t)(uint8_t)r0 | ((uint32_t)(uint8_t)r1 << 8) |
                             ((uint32_t)(uint8_t)r2 << 16) | ((uint32_t)(uint8_t)r3 << 24);
    }
}

// ---------------- kernel 5: int8 mma.sync GEMM ----------------
// CTA tile 128(M) x 256(N), K-step 64, 4 stages cp.async.
// 8 warps, warp tile 64x64 (warp grid 2M x 4N).
// SMEM per stage: A 128x64 (8 KB) + B 256x64 (16 KB) = 24 KB; 4 stages = 96 KB.
#define CTA_M 128
#define CTA_N 256
#define KSTEP 64
#define STAGES 4
#define STAGE_BYTES 24576
#define A_BYTES 8192
#define GEMM_SMEM (STAGES * STAGE_BYTES)

// swizzled byte offset within a tile whose rows are 64B (k-major)
__device__ __forceinline__ int sw_off(int row, int col) {
    int chunk = ((col >> 4) ^ (row & 3) ^ ((row >> 2) & 1)) & 3;
    return row * 64 + chunk * 16 + (col & 15);
}

__global__ __launch_bounds__(256, 1) void gemm_kernel(float* __restrict__ out) {
    extern __shared__ int8_t smem[];
    const int tid = threadIdx.x;
    const int wid = tid >> 5, lane = tid & 31;
    const int wm = wid & 1, wn = wid >> 1;          // warp grid 2(M) x 4(N)
    const int tileM = blockIdx.y, tileN = blockIdx.x;

    const int8_t* Ab = g_xq8 + (size_t)(tileM * CTA_M) * K_DIM;
    const int8_t* Bb = g_wq8 + (size_t)(tileN * CTA_N) * K_DIM;

    auto load_stage = [&](int s, int it) {
        int8_t* sa = smem + s * STAGE_BYTES;
        int8_t* sbp = sa + A_BYTES;
        const int k0 = it * KSTEP;
#pragma unroll
        for (int i = 0; i < 2; ++i) {               // A: 512 x 16B chunks
            int c = tid + i * 256;
            int row = c >> 2, ch = c & 3;
            int sch = (ch ^ (row & 3) ^ ((row >> 2) & 1)) & 3;
            cp_async16(smem_u32(sa + row * 64 + sch * 16),
                       Ab + (size_t)row * K_DIM + k0 + ch * 16);
        }
#pragma unroll
        for (int i = 0; i < 4; ++i) {               // B: 1024 x 16B chunks
            int c = tid + i * 256;
            int row = c >> 2, ch = c & 3;
            int sch = (ch ^ (row & 3) ^ ((row >> 2) & 1)) & 3;
            cp_async16(smem_u32(sbp + row * 64 + sch * 16),
                       Bb + (size_t)row * K_DIM + k0 + ch * 16);
        }
        asm volatile("cp.async.commit_group;" ::: "memory");
    };

    int acc[32][4];
#pragma unroll
    for (int i = 0; i < 32; ++i)
#pragma unroll
        for (int j = 0; j < 4; ++j) acc[i][j] = 0;

    load_stage(0, 0);
    load_stage(1, 1);
    load_stage(2, 2);

    const int qrow = lane >> 2;        // 0..7
    const int qcol = (lane & 3) * 4;   // 0,4,8,12

    for (int it = 0; it < 64; ++it) {
        asm volatile("cp.async.wait_group 2;" ::: "memory");
        __syncthreads();
        const int8_t* sa = smem + (it & 3) * STAGE_BYTES;
        const int8_t* sb = sa + A_BYTES;
#pragma unroll
        for (int kk = 0; kk < 2; ++kk) {
            const int kb = kk * 32;
            uint32_t afr[4][4];
#pragma unroll
            for (int mt = 0; mt < 4; ++mt) {
                int r0 = wm * 64 + mt * 16 + qrow;
                afr[mt][0] = *(const uint32_t*)(sa + sw_off(r0,     kb + qcol));
                afr[mt][1] = *(const uint32_t*)(sa + sw_off(r0 + 8, kb + qcol));
                afr[mt][2] = *(const uint32_t*)(sa + sw_off(r0,     kb + qcol + 16));
                afr[mt][3] = *(const uint32_t*)(sa + sw_off(r0 + 8, kb + qcol + 16));
            }
            uint32_t bfr[8][2];
#pragma unroll
            for (int nt = 0; nt < 8; ++nt) {
                int nr = wn * 64 + nt * 8 + qrow;
                bfr[nt][0] = *(const uint32_t*)(sb + sw_off(nr, kb + qcol));
                bfr[nt][1] = *(const uint32_t*)(sb + sw_off(nr, kb + qcol + 16));
            }
#pragma unroll
            for (int mt = 0; mt < 4; ++mt)
#pragma unroll
                for (int nt = 0; nt < 8; ++nt)
                    mma_s8(acc[mt * 8 + nt], afr[mt], bfr[nt]);
        }
        __syncthreads();
        if (it + 3 < 64) load_stage((it + 3) & 3, it + 3);
        else asm volatile("cp.async.commit_group;" ::: "memory");
    }

    // epilogue: out[m][n] = acc * gamma[m] * alpha / 127
    const float scA = g_alpha * (1.0f / 127.0f);
#pragma unroll
    for (int mt = 0; mt < 4; ++mt) {
        const int r0 = tileM * CTA_M + wm * 64 + mt * 16 + qrow;
        const float s0 = g_gamma[r0] * scA;
        const float s1 = g_gamma[r0 + 8] * scA;
        float* o0 = out + (size_t)r0 * N_DIM;
        float* o1 = out + (size_t)(r0 + 8) * N_DIM;
#pragma unroll
        for (int nt = 0; nt < 8; ++nt) {
            const int nc = tileN * CTA_N + wn * 64 + nt * 8 + (lane & 3) * 2;
            const int* c = acc[mt * 8 + nt];
            float2 v0 = make_float2((float)c[0] * s0, (float)c[1] * s0);
            float2 v1 = make_float2((float)c[2] * s1, (float)c[3] * s1);
            *reinterpret_cast<float2*>(o0 + nc) = v0;
            *reinterpret_cast<float2*>(o1 + nc) = v1;
        }
    }
}

// ---------------- launch ----------------
extern "C" void kernel_launch(void* const* d_in, const int* in_sizes, int n_in,
                              void* d_out, int out_size) {
    const float* x = (const float*)d_in[0];
    const float* w = (const float*)d_in[1];
    if (n_in >= 2 && in_sizes[0] == N_DIM * K_DIM) {  // defensive: order per metadata
        x = (const float*)d_in[1];
        w = (const float*)d_in[0];
    }
    float* out = (float*)d_out;

    absmean_partial_kernel<<<1024, 256>>>(w);
    absmean_final_kernel<<<1, 256>>>();
    quant_w_kernel<<<2048, 256>>>(w);
    quant_x_kernel<<<8192, 256>>>(x);

    cudaFuncSetAttribute(gemm_kernel, cudaFuncAttributeMaxDynamicSharedMemorySize, GEMM_SMEM);
    gemm_kernel<<<dim3(N_DIM / CTA_N, M_DIM / CTA_M), 256, GEMM_SMEM>>>(out);
}

// round 14
// speedup vs baseline: 1.0101x; 1.0101x over previous
#include <cuda_runtime.h>
#include <cstdint>

#define M_DIM 8192
#define N_DIM 16384
#define K_DIM 4096

// ---------------- device scratch (no allocations allowed) ----------------
__device__ int8_t g_xq8[(size_t)M_DIM * K_DIM];   // 32 MB quantized activations (ints)
__device__ int8_t g_wq8[(size_t)N_DIM * K_DIM];   // 64 MB ternary weights
__device__ float g_gamma[M_DIM];
__device__ float g_partial[1024];
__device__ float g_alpha;

// ---------------- helpers ----------------
__device__ __forceinline__ uint32_t smem_u32(const void* p) {
    uint32_t a;
    asm("{ .reg .u64 t; cvta.to.shared.u64 t, %1; cvt.u32.u64 %0, t; }" : "=r"(a) : "l"(p));
    return a;
}
__device__ __forceinline__ void cp_async16(uint32_t s, const void* g) {
    asm volatile("cp.async.cg.shared.global [%0], [%1], 16;" :: "r"(s), "l"(g) : "memory");
}
__device__ __forceinline__ void mma_s8(int* c, const uint32_t* a, const uint32_t* b) {
    asm volatile(
        "mma.sync.aligned.m16n8k32.row.col.s32.s8.s8.s32 "
        "{%0,%1,%2,%3}, {%4,%5,%6,%7}, {%8,%9}, {%0,%1,%2,%3};"
        : "+r"(c[0]), "+r"(c[1]), "+r"(c[2]), "+r"(c[3])
        : "r"(a[0]), "r"(a[1]), "r"(a[2]), "r"(a[3]), "r"(b[0]), "r"(b[1]));
}
__device__ __forceinline__ void ldmx4(uint32_t* r, uint32_t addr) {
    asm volatile("ldmatrix.sync.aligned.m8n8.x4.shared.b16 {%0,%1,%2,%3}, [%4];"
                 : "=r"(r[0]), "=r"(r[1]), "=r"(r[2]), "=r"(r[3]) : "r"(addr));
}

// ---------------- kernel 1: partial sums of |w| (fixed order -> deterministic) ----------------
__global__ __launch_bounds__(256) void absmean_partial_kernel(const float* __restrict__ w) {
    __shared__ float red[256];
    const float4* w4 = reinterpret_cast<const float4*>(w);
    float s = 0.f;
    const int stride = gridDim.x * blockDim.x;
    for (int i = blockIdx.x * blockDim.x + threadIdx.x; i < 16777216; i += stride) {
        float4 v = w4[i];
        s += fabsf(v.x) + fabsf(v.y) + fabsf(v.z) + fabsf(v.w);
    }
    red[threadIdx.x] = s;
    __syncthreads();
    for (int o = 128; o > 0; o >>= 1) {
        if (threadIdx.x < (unsigned)o) red[threadIdx.x] += red[threadIdx.x + o];
        __syncthreads();
    }
    if (threadIdx.x == 0) g_partial[blockIdx.x] = red[0];
}

// ---------------- kernel 2: alpha ----------------
__global__ __launch_bounds__(256) void absmean_final_kernel() {
    __shared__ float red[256];
    float s = 0.f;
#pragma unroll
    for (int t = 0; t < 4; ++t) s += g_partial[threadIdx.x + t * 256];
    red[threadIdx.x] = s;
    __syncthreads();
    for (int o = 128; o > 0; o >>= 1) {
        if (threadIdx.x < (unsigned)o) red[threadIdx.x] += red[threadIdx.x + o];
        __syncthreads();
    }
    if (threadIdx.x == 0) g_alpha = red[0] * (1.0f / 67108864.0f) + 1e-8f;
}

// ---------------- kernel 3: fused quant (x rows + w ternary) ----------------
__global__ __launch_bounds__(256) void fused_quant_kernel(const float* __restrict__ x,
                                                          const float* __restrict__ w) {
    const int tid = threadIdx.x;
    if (blockIdx.x < M_DIM) {
        // ---- activation row quant ----
        __shared__ float red[256];
        const int row = blockIdx.x;
        const float4* xr = reinterpret_cast<const float4*>(x + (size_t)row * K_DIM);
        float4 v[4];
        float mx = 0.f;
#pragma unroll
        for (int t = 0; t < 4; ++t) {
            v[t] = xr[tid + t * 256];
            mx = fmaxf(mx, fmaxf(fmaxf(fabsf(v[t].x), fabsf(v[t].y)),
                                 fmaxf(fabsf(v[t].z), fabsf(v[t].w))));
        }
        red[tid] = mx;
        __syncthreads();
        for (int o = 128; o > 0; o >>= 1) {
            if (tid < (unsigned)o) red[tid] = fmaxf(red[tid], red[tid + o]);
            __syncthreads();
        }
        const float gamma = fmaxf(red[0], 1e-8f);
        if (tid == 0) g_gamma[row] = gamma;
        const float sc = 127.0f / gamma;
        uint32_t* dst = reinterpret_cast<uint32_t*>(g_xq8 + (size_t)row * K_DIM);
#pragma unroll
        for (int t = 0; t < 4; ++t) {
            int r0 = __float2int_rn(v[t].x * sc);
            int r1 = __float2int_rn(v[t].y * sc);
            int r2 = __float2int_rn(v[t].z * sc);
            int r3 = __float2int_rn(v[t].w * sc);
            dst[tid + t * 256] = (uint32_t)(uint8_t)r0 | ((uint32_t)(uint8_t)r1 << 8) |
                                 ((uint32_t)(uint8_t)r2 << 16) | ((uint32_t)(uint8_t)r3 << 24);
        }
    } else {
        // ---- ternary weight quant ----
        const float inv_a = 1.0f / g_alpha;
        const float4* w4 = reinterpret_cast<const float4*>(w);
        uint32_t* dst = reinterpret_cast<uint32_t*>(g_wq8);
        const int nblk = gridDim.x - M_DIM;
        const int stride = nblk * 256;
        for (int i = (blockIdx.x - M_DIM) * 256 + tid; i < 16777216; i += stride) {
            float4 v = w4[i];
            int r0 = min(max(__float2int_rn(v.x * inv_a), -1), 1);
            int r1 = min(max(__float2int_rn(v.y * inv_a), -1), 1);
            int r2 = min(max(__float2int_rn(v.z * inv_a), -1), 1);
            int r3 = min(max(__float2int_rn(v.w * inv_a), -1), 1);
            dst[i] = (uint32_t)(uint8_t)r0 | ((uint32_t)(uint8_t)r1 << 8) |
                     ((uint32_t)(uint8_t)r2 << 16) | ((uint32_t)(uint8_t)r3 << 24);
        }
    }
}

// ---------------- kernel 4: int8 mma.sync GEMM ----------------
// CTA tile 128(M) x 256(N), K-step 64, 4 stages cp.async.
// 8 warps, warp tile 64x64 (warp grid 2M x 4N). ldmatrix fragment loads.
// SMEM per stage: A 128x64 (8 KB) + B 256x64 (16 KB) = 24 KB; 4 stages = 96 KB.
#define CTA_M 128
#define CTA_N 256
#define KSTEP 64
#define STAGE_BYTES 24576
#define A_BYTES 8192
#define GEMM_SMEM (4 * STAGE_BYTES)

__global__ __launch_bounds__(256, 1) void gemm_kernel(float* __restrict__ out) {
    extern __shared__ int8_t smem[];
    const uint32_t smem_b = smem_u32(smem);
    const int tid = threadIdx.x;
    const int wid = tid >> 5, lane = tid & 31;
    const int wm = wid & 1, wn = wid >> 1;          // warp grid 2(M) x 4(N)
    const int tileM = blockIdx.y, tileN = blockIdx.x;

    const int8_t* Ab = g_xq8 + (size_t)(tileM * CTA_M) * K_DIM;
    const int8_t* Bb = g_wq8 + (size_t)(tileN * CTA_N) * K_DIM;

    auto load_stage = [&](int s, int it) {
        uint32_t sa = smem_b + s * STAGE_BYTES;
        uint32_t sbp = sa + A_BYTES;
        const int k0 = it * KSTEP;
#pragma unroll
        for (int i = 0; i < 2; ++i) {               // A: 512 x 16B chunks
            int c = tid + i * 256;
            int row = c >> 2, ch = c & 3;
            int sch = (ch ^ (row & 3) ^ ((row >> 2) & 1)) & 3;
            cp_async16(sa + row * 64 + sch * 16, Ab + (size_t)row * K_DIM + k0 + ch * 16);
        }
#pragma unroll
        for (int i = 0; i < 4; ++i) {               // B: 1024 x 16B chunks
            int c = tid + i * 256;
            int row = c >> 2, ch = c & 3;
            int sch = (ch ^ (row & 3) ^ ((row >> 2) & 1)) & 3;
            cp_async16(sbp + row * 64 + sch * 16, Bb + (size_t)row * K_DIM + k0 + ch * 16);
        }
        asm volatile("cp.async.commit_group;" ::: "memory");
    };

    int acc[32][4];
#pragma unroll
    for (int i = 0; i < 32; ++i)
#pragma unroll
        for (int j = 0; j < 4; ++j) acc[i][j] = 0;

    load_stage(0, 0);
    load_stage(1, 1);
    load_stage(2, 2);

    // ldmatrix lane roles (derived to match the m16n8k32 fragment layout):
    // A (x4): lanes 0-15 -> rows 0-15 of tile @k-chunk0, lanes 16-31 -> same rows @k-chunk1
    const int l15 = lane & 15, lhiA = lane >> 4;
    const int aswz = (l15 & 3) ^ ((l15 >> 2) & 1);
    // B (x4): m0,m1 = nt rows @k0,@k16 ; m2,m3 = nt+1 rows @k0,@k16
    const int l7 = lane & 7, selB = (lane >> 3) & 1, ntoffB = lane >> 4;
    const int bswz = (l7 & 3) ^ ((l7 >> 2) & 1);

    for (int it = 0; it < 64; ++it) {
        asm volatile("cp.async.wait_group 2;" ::: "memory");
        __syncthreads();
        if (it + 3 < 64) load_stage((it + 3) & 3, it + 3);
        else asm volatile("cp.async.commit_group;" ::: "memory");

        const uint32_t sa = smem_b + (it & 3) * STAGE_BYTES;
        const uint32_t sb = sa + A_BYTES;
#pragma unroll
        for (int kk = 0; kk < 2; ++kk) {
            const int chA = ((kk * 2 + lhiA) ^ aswz) & 3;
            const uint32_t aBase = sa + (uint32_t)((wm * 64 + l15) * 64 + chA * 16);
            uint32_t afr[4][4];
#pragma unroll
            for (int mt = 0; mt < 4; ++mt) ldmx4(afr[mt], aBase + mt * 1024);

            const int chB = ((kk * 2 + selB) ^ bswz) & 3;
            const uint32_t bBase = sb + (uint32_t)((wn * 64 + ntoffB * 8 + l7) * 64 + chB * 16);
            uint32_t bfr[4][4];   // [ntp][m0..m3]: {nt b0, nt b1, nt+1 b0, nt+1 b1}
#pragma unroll
            for (int ntp = 0; ntp < 4; ++ntp) ldmx4(bfr[ntp], bBase + ntp * 1024);

#pragma unroll
            for (int mt = 0; mt < 4; ++mt)
#pragma unroll
                for (int ntp = 0; ntp < 4; ++ntp) {
                    mma_s8(acc[mt * 8 + ntp * 2],     afr[mt], &bfr[ntp][0]);
                    mma_s8(acc[mt * 8 + ntp * 2 + 1], afr[mt], &bfr[ntp][2]);
                }
        }
    }

    // epilogue: out[m][n] = acc * gamma[m] * alpha / 127
    const int qrow = lane >> 2;
    const float scA = g_alpha * (1.0f / 127.0f);
#pragma unroll
    for (int mt = 0; mt < 4; ++mt) {
        const int r0 = tileM * CTA_M + wm * 64 + mt * 16 + qrow;
        const float s0 = g_gamma[r0] * scA;
        const float s1 = g_gamma[r0 + 8] * scA;
        float* o0 = out + (size_t)r0 * N_DIM;
        float* o1 = out + (size_t)(r0 + 8) * N_DIM;
#pragma unroll
        for (int nt = 0; nt < 8; ++nt) {
            const int nc = tileN * CTA_N + wn * 64 + nt * 8 + (lane & 3) * 2;
            const int* c = acc[mt * 8 + nt];
            float2 v0 = make_float2((float)c[0] * s0, (float)c[1] * s0);
            float2 v1 = make_float2((float)c[2] * s1, (float)c[3] * s1);
            *reinterpret_cast<float2*>(o0 + nc) = v0;
            *reinterpret_cast<float2*>(o1 + nc) = v1;
        }
    }
}

// ---------------- launch ----------------
extern "C" void kernel_launch(void* const* d_in, const int* in_sizes, int n_in,
                              void* d_out, int out_size) {
    const float* x = (const float*)d_in[0];
    const float* w = (const float*)d_in[1];
    if (n_in >= 2 && in_sizes[0] == N_DIM * K_DIM) {  // defensive: order per metadata
        x = (const float*)d_in[1];
        w = (const float*)d_in[0];
    }
    float* out = (float*)d_out;

    absmean_partial_kernel<<<1024, 256>>>(w);
    absmean_final_kernel<<<1, 256>>>();
    fused_quant_kernel<<<M_DIM + 2048, 256>>>(x, w);

    cudaFuncSetAttribute(gemm_kernel, cudaFuncAttributeMaxDynamicSharedMemorySize, GEMM_SMEM);
    gemm_kernel<<<dim3(N_DIM / CTA_N, M_DIM / CTA_M), 256, GEMM_SMEM>>>(out);
}

// round 15
// speedup vs baseline: 1.2791x; 1.2663x over previous
#include <cuda_runtime.h>
#include <cstdint>

#define M_DIM 8192
#define N_DIM 16384
#define K_DIM 4096

// ---------------- device scratch (no allocations allowed) ----------------
__device__ int8_t g_xq8[(size_t)M_DIM * K_DIM];   // 32 MB quantized activations (ints)
__device__ int8_t g_wq8[(size_t)N_DIM * K_DIM];   // 64 MB ternary weights
__device__ float g_gamma[M_DIM];
__device__ float g_partial[1024];
__device__ float g_alpha;

// ---------------- helpers ----------------
__device__ __forceinline__ uint32_t smem_u32(const void* p) {
    uint32_t a;
    asm("{ .reg .u64 t; cvta.to.shared.u64 t, %1; cvt.u32.u64 %0, t; }" : "=r"(a) : "l"(p));
    return a;
}
__device__ __forceinline__ void cp_async16(uint32_t s, const void* g) {
    asm volatile("cp.async.cg.shared.global [%0], [%1], 16;" :: "r"(s), "l"(g) : "memory");
}
__device__ __forceinline__ void mma_s8(int* c, const uint32_t* a, const uint32_t* b) {
    asm volatile(
        "mma.sync.aligned.m16n8k32.row.col.s32.s8.s8.s32 "
        "{%0,%1,%2,%3}, {%4,%5,%6,%7}, {%8,%9}, {%0,%1,%2,%3};"
        : "+r"(c[0]), "+r"(c[1]), "+r"(c[2]), "+r"(c[3])
        : "r"(a[0]), "r"(a[1]), "r"(a[2]), "r"(a[3]), "r"(b[0]), "r"(b[1]));
}
__device__ __forceinline__ void ldmx4(uint32_t* r, uint32_t addr) {
    asm volatile("ldmatrix.sync.aligned.m8n8.x4.shared.b16 {%0,%1,%2,%3}, [%4];"
                 : "=r"(r[0]), "=r"(r[1]), "=r"(r[2]), "=r"(r[3]) : "r"(addr));
}

// ---------------- kernel 1: partial sums of |w| (fixed order -> deterministic) ----------------
__global__ __launch_bounds__(256) void absmean_partial_kernel(const float* __restrict__ w) {
    __shared__ float red[256];
    const float4* w4 = reinterpret_cast<const float4*>(w);
    float s = 0.f;
    const int stride = gridDim.x * blockDim.x;
    for (int i = blockIdx.x * blockDim.x + threadIdx.x; i < 16777216; i += stride) {
        float4 v = w4[i];
        s += fabsf(v.x) + fabsf(v.y) + fabsf(v.z) + fabsf(v.w);
    }
    red[threadIdx.x] = s;
    __syncthreads();
    for (int o = 128; o > 0; o >>= 1) {
        if (threadIdx.x < (unsigned)o) red[threadIdx.x] += red[threadIdx.x + o];
        __syncthreads();
    }
    if (threadIdx.x == 0) g_partial[blockIdx.x] = red[0];
}

// ---------------- kernel 2: alpha ----------------
__global__ __launch_bounds__(256) void absmean_final_kernel() {
    __shared__ float red[256];
    float s = 0.f;
#pragma unroll
    for (int t = 0; t < 4; ++t) s += g_partial[threadIdx.x + t * 256];
    red[threadIdx.x] = s;
    __syncthreads();
    for (int o = 128; o > 0; o >>= 1) {
        if (threadIdx.x < (unsigned)o) red[threadIdx.x] += red[threadIdx.x + o];
        __syncthreads();
    }
    if (threadIdx.x == 0) g_alpha = red[0] * (1.0f / 67108864.0f) + 1e-8f;
}

// ---------------- kernel 3: fused quant (x rows + w ternary) ----------------
__global__ __launch_bounds__(256) void fused_quant_kernel(const float* __restrict__ x,
                                                          const float* __restrict__ w) {
    const int tid = threadIdx.x;
    if (blockIdx.x < M_DIM) {
        __shared__ float red[256];
        const int row = blockIdx.x;
        const float4* xr = reinterpret_cast<const float4*>(x + (size_t)row * K_DIM);
        float4 v[4];
        float mx = 0.f;
#pragma unroll
        for (int t = 0; t < 4; ++t) {
            v[t] = xr[tid + t * 256];
            mx = fmaxf(mx, fmaxf(fmaxf(fabsf(v[t].x), fabsf(v[t].y)),
                                 fmaxf(fabsf(v[t].z), fabsf(v[t].w))));
        }
        red[tid] = mx;
        __syncthreads();
        for (int o = 128; o > 0; o >>= 1) {
            if (tid < (unsigned)o) red[tid] = fmaxf(red[tid], red[tid + o]);
            __syncthreads();
        }
        const float gamma = fmaxf(red[0], 1e-8f);
        if (tid == 0) g_gamma[row] = gamma;
        const float sc = 127.0f / gamma;
        uint32_t* dst = reinterpret_cast<uint32_t*>(g_xq8 + (size_t)row * K_DIM);
#pragma unroll
        for (int t = 0; t < 4; ++t) {
            int r0 = __float2int_rn(v[t].x * sc);
            int r1 = __float2int_rn(v[t].y * sc);
            int r2 = __float2int_rn(v[t].z * sc);
            int r3 = __float2int_rn(v[t].w * sc);
            dst[tid + t * 256] = (uint32_t)(uint8_t)r0 | ((uint32_t)(uint8_t)r1 << 8) |
                                 ((uint32_t)(uint8_t)r2 << 16) | ((uint32_t)(uint8_t)r3 << 24);
        }
    } else {
        const float inv_a = 1.0f / g_alpha;
        const float4* w4 = reinterpret_cast<const float4*>(w);
        uint32_t* dst = reinterpret_cast<uint32_t*>(g_wq8);
        const int nblk = gridDim.x - M_DIM;
        const int stride = nblk * 256;
        for (int i = (blockIdx.x - M_DIM) * 256 + tid; i < 16777216; i += stride) {
            float4 v = w4[i];
            int r0 = min(max(__float2int_rn(v.x * inv_a), -1), 1);
            int r1 = min(max(__float2int_rn(v.y * inv_a), -1), 1);
            int r2 = min(max(__float2int_rn(v.z * inv_a), -1), 1);
            int r3 = min(max(__float2int_rn(v.w * inv_a), -1), 1);
            dst[i] = (uint32_t)(uint8_t)r0 | ((uint32_t)(uint8_t)r1 << 8) |
                     ((uint32_t)(uint8_t)r2 << 16) | ((uint32_t)(uint8_t)r3 << 24);
        }
    }
}

// ---------------- kernel 4: hybrid tensor(mma.sync) + dp4a GEMM ----------------
// CTA 128(M) x 256(N), KSTEP 64, 4 stages. 8 warps:
//   warps 0-3: tensor, N[0,160), warp tile 64x80 (grid 2M x 2N)
//   warps 4-7: dp4a,  N[160,256), warp tile 64x48 (grid 2M x 2N), thread tile 8x12
#define CTA_M 128
#define CTA_N 256
#define KSTEP 64
#define STAGE_BYTES 24576
#define A_BYTES 8192
#define GEMM_SMEM (4 * STAGE_BYTES)

__global__ __launch_bounds__(256, 1) void gemm_kernel(float* __restrict__ out) {
    extern __shared__ int8_t smem[];
    const uint32_t smem_b = smem_u32(smem);
    const int tid = threadIdx.x;
    const int wid = tid >> 5, lane = tid & 31;
    const int tileM = blockIdx.y, tileN = blockIdx.x;

    const int8_t* Ab = g_xq8 + (size_t)(tileM * CTA_M) * K_DIM;
    const int8_t* Bb = g_wq8 + (size_t)(tileN * CTA_N) * K_DIM;

    auto load_stage = [&](int s, int it) {
        uint32_t sa = smem_b + s * STAGE_BYTES;
        uint32_t sbp = sa + A_BYTES;
        const int k0 = it * KSTEP;
#pragma unroll
        for (int i = 0; i < 2; ++i) {               // A: 512 x 16B chunks
            int c = tid + i * 256;
            int row = c >> 2, ch = c & 3;
            int sch = (ch ^ (row & 3) ^ ((row >> 2) & 1)) & 3;
            cp_async16(sa + row * 64 + sch * 16, Ab + (size_t)row * K_DIM + k0 + ch * 16);
        }
#pragma unroll
        for (int i = 0; i < 4; ++i) {               // B: 1024 x 16B chunks
            int c = tid + i * 256;
            int row = c >> 2, ch = c & 3;
            int sch = (ch ^ (row & 3) ^ ((row >> 2) & 1)) & 3;
            cp_async16(sbp + row * 64 + sch * 16, Bb + (size_t)row * K_DIM + k0 + ch * 16);
        }
        asm volatile("cp.async.commit_group;" ::: "memory");
    };

    // shared accumulator file: tensor uses all 160, dp4a uses first 96
    int acc[160];
#pragma unroll
    for (int i = 0; i < 160; ++i) acc[i] = 0;

    load_stage(0, 0);
    load_stage(1, 1);
    load_stage(2, 2);

    const bool is_tensor = (wid < 4);
    const int wm = wid & 1, wn = (wid >> 1) & 1;

    // tensor ldmatrix lane roles
    const int l15 = lane & 15, lhiA = lane >> 4;
    const int aswz = (l15 & 3) ^ ((l15 >> 2) & 1);
    const int l7 = lane & 7, selB = (lane >> 3) & 1, ntoffB = lane >> 4;
    const int bswz = (l7 & 3) ^ ((l7 >> 2) & 1);

    // dp4a lane roles: thread rows m = wm*64 + tr + 8i, cols n = 160 + wn*48 + tc + 4j
    const int tr = lane >> 2, tc = lane & 3;

    for (int it = 0; it < 64; ++it) {
        asm volatile("cp.async.wait_group 2;" ::: "memory");
        __syncthreads();
        if (it + 3 < 64) load_stage((it + 3) & 3, it + 3);
        else asm volatile("cp.async.commit_group;" ::: "memory");

        const uint32_t sa = smem_b + (it & 3) * STAGE_BYTES;
        const uint32_t sb = sa + A_BYTES;

        if (is_tensor) {
#pragma unroll
            for (int kk = 0; kk < 2; ++kk) {
                const int chA = ((kk * 2 + lhiA) ^ aswz) & 3;
                const uint32_t aBase = sa + (uint32_t)((wm * 64 + l15) * 64 + chA * 16);
                uint32_t afr[4][4];
#pragma unroll
                for (int mt = 0; mt < 4; ++mt) ldmx4(afr[mt], aBase + mt * 1024);

                const int chB = ((kk * 2 + selB) ^ bswz) & 3;
                const uint32_t bBase =
                    sb + (uint32_t)((wn * 80 + ntoffB * 8 + l7) * 64 + chB * 16);
                uint32_t bfr[5][4];
#pragma unroll
                for (int ntp = 0; ntp < 5; ++ntp) ldmx4(bfr[ntp], bBase + ntp * 1024);

#pragma unroll
                for (int mt = 0; mt < 4; ++mt)
#pragma unroll
                    for (int ntp = 0; ntp < 5; ++ntp) {
                        mma_s8(&acc[(mt * 10 + ntp * 2) * 4],     afr[mt], &bfr[ntp][0]);
                        mma_s8(&acc[(mt * 10 + ntp * 2 + 1) * 4], afr[mt], &bfr[ntp][2]);
                    }
            }
        } else {
#pragma unroll
            for (int kc = 0; kc < 16; ++kc) {
                const int chkc = kc >> 2, offkc = (kc & 3) * 4;
                uint32_t av[8], bv[12];
#pragma unroll
                for (int i = 0; i < 8; ++i) {
                    int m = wm * 64 + tr + 8 * i;
                    int sch = (chkc ^ (m & 3) ^ ((m >> 2) & 1)) & 3;
                    av[i] = *(const uint32_t*)(smem + ((sa - smem_b) + m * 64 + sch * 16 + offkc));
                }
#pragma unroll
                for (int j = 0; j < 12; ++j) {
                    int n = 160 + wn * 48 + tc + 4 * j;
                    int sch = (chkc ^ (n & 3) ^ ((n >> 2) & 1)) & 3;
                    bv[j] = *(const uint32_t*)(smem + ((sb - smem_b) + n * 64 + sch * 16 + offkc));
                }
#pragma unroll
                for (int i = 0; i < 8; ++i)
#pragma unroll
                    for (int j = 0; j < 12; ++j)
                        acc[i * 12 + j] = __dp4a((int)av[i], (int)bv[j], acc[i * 12 + j]);
            }
        }
    }

    // ---------------- epilogue ----------------
    const float scA = g_alpha * (1.0f / 127.0f);
    if (is_tensor) {
        const int qrow = lane >> 2;
#pragma unroll
        for (int mt = 0; mt < 4; ++mt) {
            const int r0 = tileM * CTA_M + wm * 64 + mt * 16 + qrow;
            const float s0 = g_gamma[r0] * scA;
            const float s1 = g_gamma[r0 + 8] * scA;
            float* o0 = out + (size_t)r0 * N_DIM;
            float* o1 = out + (size_t)(r0 + 8) * N_DIM;
#pragma unroll
            for (int nt = 0; nt < 10; ++nt) {
                const int nc = tileN * CTA_N + wn * 80 + nt * 8 + (lane & 3) * 2;
                const int* c = &acc[(mt * 10 + nt) * 4];
                float2 v0 = make_float2((float)c[0] * s0, (float)c[1] * s0);
                float2 v1 = make_float2((float)c[2] * s1, (float)c[3] * s1);
                *reinterpret_cast<float2*>(o0 + nc) = v0;
                *reinterpret_cast<float2*>(o1 + nc) = v1;
            }
        }
    } else {
#pragma unroll
        for (int i = 0; i < 8; ++i) {
            const int m = tileM * CTA_M + wm * 64 + tr + 8 * i;
            const float s = g_gamma[m] * scA;
            float* orow = out + (size_t)m * N_DIM + tileN * CTA_N + 160 + wn * 48 + tc;
#pragma unroll
            for (int j = 0; j < 12; ++j)
                orow[4 * j] = (float)acc[i * 12 + j] * s;
        }
    }
}

// ---------------- launch ----------------
extern "C" void kernel_launch(void* const* d_in, const int* in_sizes, int n_in,
                              void* d_out, int out_size) {
    const float* x = (const float*)d_in[0];
    const float* w = (const float*)d_in[1];
    if (n_in >= 2 && in_sizes[0] == N_DIM * K_DIM) {  // defensive: order per metadata
        x = (const float*)d_in[1];
        w = (const float*)d_in[0];
    }
    float* out = (float*)d_out;

    absmean_partial_kernel<<<1024, 256>>>(w);
    absmean_final_kernel<<<1, 256>>>();
    fused_quant_kernel<<<M_DIM + 2048, 256>>>(x, w);

    cudaFuncSetAttribute(gemm_kernel, cudaFuncAttributeMaxDynamicSharedMemorySize, GEMM_SMEM);
    gemm_kernel<<<dim3(N_DIM / CTA_N, M_DIM / CTA_M), 256, GEMM_SMEM>>>(out);
}